// round 16
// baseline (speedup 1.0000x reference)
#include <cuda_runtime.h>
#include <cuda_bf16.h>
#include <math.h>

#define B_TOT 4096
#define T_LEN 32
#define DDIM 15
#define NSTEPS 5
#define DT_C 0.2f

// fused kernel config
#define GRU_RPB 32
#define GRU_NBLK (B_TOT / GRU_RPB)
#define KS 168
#define KSB 336
#define WOFF 10752
#define GRU_SMEM (10752 + 512 * KSB)
// SDE smem offsets (reuse weight region after GRU finishes)
#define SPAD 36
#define SOFF_INP 10752                 // [106][36] f32 = 15264 B
#define SOFF_B1  26016                 // [128][36] f32 = 18432 B
#define SOFF_B2  44448                 // [128][36] f32

typedef unsigned long long ull;
typedef unsigned int u32;
typedef unsigned short u16;

__device__ __forceinline__ float tanhapx(float x) {
    float y; asm("tanh.approx.f32 %0, %1;" : "=f"(y) : "f"(x)); return y;
}
__device__ __forceinline__ float fsig(float x) { return fmaf(0.5f, tanhapx(0.5f * x), 0.5f); }
__device__ __forceinline__ float ftanh(float x) { return tanhapx(x); }
__device__ __forceinline__ float bf2f(u16 b) { return __uint_as_float(((u32)b) << 16); }

// ---------------- packed f32x2 helpers -------------------------------------------
__device__ __forceinline__ void fma2(ull& acc, ull a, ull b) {
    asm("fma.rn.f32x2 %0, %1, %2, %0;" : "+l"(acc) : "l"(a), "l"(b));
}
__device__ __forceinline__ ull pack2f(float w) {
    ull r; asm("mov.b64 %0, {%1, %1};" : "=l"(r) : "r"(__float_as_uint(w))); return r;
}
__device__ __forceinline__ ull bplo(u32 u) {
    u32 f = u << 16; ull r; asm("mov.b64 %0, {%1, %1};" : "=l"(r) : "r"(f)); return r;
}
__device__ __forceinline__ ull bphi(u32 u) {
    u32 f = u & 0xFFFF0000u; ull r; asm("mov.b64 %0, {%1, %1};" : "=l"(r) : "r"(f)); return r;
}
__device__ __forceinline__ float2 unpack2(ull v) {
    float2 f; asm("mov.b64 {%0, %1}, %2;" : "=f"(f.x), "=f"(f.y) : "l"(v)); return f;
}

// ---------------- weight scratch ------------------------------------------------
__device__ __align__(16) u32 g_dr0C[4096];
__device__ __align__(16) u32 g_df0C[4096];
__device__ __align__(16) u32 g_dr0D[2048];
__device__ __align__(16) u32 g_df0D[2048];
__device__ __align__(16) u32 g_dr1P[8192];
__device__ __align__(16) u32 g_dr2P[8192];
__device__ __align__(16) u32 g_df1P[8192];
__device__ float g_dr3T[128 * 15];
__device__ float g_df2T[128 * 15];
__device__ float g_projT[128 * 64];
__device__ __align__(16) u16 g_wmma[512 * KS];

__device__ __forceinline__ u32 bfbits(float w) {
    __nv_bfloat16 h = __float2bfloat16(w);
    return (u32)__bfloat16_as_ushort(h);
}
__device__ __forceinline__ u16 bf16u16(float w) {
    __nv_bfloat16 h = __float2bfloat16(w);
    return __bfloat16_as_ushort(h);
}

// ---------------- prep (unchanged packings) --------------------------------------
__global__ void prep_kernel(const float* __restrict__ wih, const float* __restrict__ whh,
                            const float* __restrict__ proj,
                            const float* __restrict__ d0, const float* __restrict__ d1,
                            const float* __restrict__ d2, const float* __restrict__ d3,
                            const float* __restrict__ f0, const float* __restrict__ f1,
                            const float* __restrict__ f2) {
    int tid = blockIdx.x * blockDim.x + threadIdx.x;
    int nt = gridDim.x * blockDim.x;

    for (int i = tid; i < 512 * KS; i += nt) {
        int n = i / KS, k = i - n * KS;
        int chunk = n >> 6, rem = n & 63, gate = rem >> 4, jr = rem & 15;
        int j = chunk * 16 + jr;
        float v = 0.f;
        if (gate == 0) {
            if (k < 25) v = wih[j * 25 + k];
            else if (k >= 32 && k < 160) v = whh[j * 128 + (k - 32)];
        } else if (gate == 1) {
            if (k < 25) v = wih[(128 + j) * 25 + k];
            else if (k >= 32 && k < 160) v = whh[(128 + j) * 128 + (k - 32)];
        } else if (gate == 2) {
            if (k < 25) v = wih[(256 + j) * 25 + k];
        } else {
            if (k >= 32 && k < 160) v = whh[(256 + j) * 128 + (k - 32)];
        }
        g_wmma[i] = bf16u16(v);
    }

    for (int i = tid; i < 4096; i += nt) {
        int t = i & 3, j = (i >> 2) & 127, kb = i >> 9;
        int kp = kb * 4 + t;
        g_dr0C[i] = bfbits(d0[j * 89 + 25 + 2 * kp]) | (bfbits(d0[j * 89 + 26 + 2 * kp]) << 16);
        g_df0C[i] = bfbits(f0[j * 89 + 25 + 2 * kp]) | (bfbits(f0[j * 89 + 26 + 2 * kp]) << 16);
    }
    for (int i = tid; i < 2048; i += nt) {
        int t = i & 3, j = (i >> 2) & 127, kb = i >> 9;
        int kp = kb * 4 + t, k0 = 2 * kp, k1 = 2 * kp + 1;
        float a0 = (k0 < 25) ? d0[j * 89 + k0] : 0.f;
        float a1 = (k1 < 25) ? d0[j * 89 + k1] : 0.f;
        g_dr0D[i] = bfbits(a0) | (bfbits(a1) << 16);
        float c0 = (k0 < 25) ? f0[j * 89 + k0] : 0.f;
        float c1 = (k1 < 25) ? f0[j * 89 + k1] : 0.f;
        g_df0D[i] = bfbits(c0) | (bfbits(c1) << 16);
    }
    for (int i = tid; i < 8192; i += nt) {
        int t = i & 3, j = (i >> 2) & 127, kb = i >> 9;
        int kp = kb * 4 + t;
        g_dr1P[i] = bfbits(d1[j * 128 + 2 * kp]) | (bfbits(d1[j * 128 + 2 * kp + 1]) << 16);
        g_dr2P[i] = bfbits(d2[j * 128 + 2 * kp]) | (bfbits(d2[j * 128 + 2 * kp + 1]) << 16);
        g_df1P[i] = bfbits(f1[j * 128 + 2 * kp]) | (bfbits(f1[j * 128 + 2 * kp + 1]) << 16);
    }
    for (int i = tid; i < 15 * 128; i += nt) { int o = i >> 7, k = i & 127; g_dr3T[k * 15 + o] = d3[i]; }
    for (int i = tid; i < 15 * 128; i += nt) { int o = i >> 7, k = i & 127; g_df2T[k * 15 + o] = f2[i]; }
    for (int i = tid; i < 64 * 128; i += nt) { int o = i >> 7, k = i & 127; g_projT[k * 64 + o] = proj[i]; }
}

// ---------------- mma helpers ----------------------------------------------------
__device__ __forceinline__ u32 smem_u32(const void* p) {
    u32 a;
    asm("{ .reg .u64 t; cvta.to.shared.u64 t, %1; cvt.u32.u64 %0, t; }" : "=r"(a) : "l"(p));
    return a;
}

#define LDSM4(R0, R1, R2, R3, ADDR) \
    asm volatile("ldmatrix.sync.aligned.m8n8.x4.shared.b16 {%0,%1,%2,%3}, [%4];" \
        : "=r"(R0), "=r"(R1), "=r"(R2), "=r"(R3) : "r"(ADDR))

#define MMAF(CACC, A0, A1, A2, A3, B0, B1) \
    asm volatile("mma.sync.aligned.m16n8k16.row.col.f32.bf16.bf16.f32 " \
        "{%0,%1,%2,%3}, {%4,%5,%6,%7}, {%8,%9}, {%0,%1,%2,%3};" \
        : "+f"((CACC)[0]), "+f"((CACC)[1]), "+f"((CACC)[2]), "+f"((CACC)[3]) \
        : "r"(A0), "r"(A1), "r"(A2), "r"(A3), "r"(B0), "r"(B1))

// ---------------- 5x5 helpers / geo ----------------------------------------------
__device__ __forceinline__ void mm5(const float* A, const float* Bm, float* Cm) {
#pragma unroll
    for (int i = 0; i < 5; i++) {
#pragma unroll
        for (int jj = 0; jj < 5; jj++) {
            float s = A[i * 5] * Bm[jj];
#pragma unroll
            for (int k = 1; k < 5; k++) s += A[i * 5 + k] * Bm[k * 5 + jj];
            Cm[i * 5 + jj] = s;
        }
    }
}

// base = &inp_s[0][lane]; sigma rows 64..88, coeff rows 90..104, stride SPAD
__device__ void geo_update(float* base) {
    const float is2 = 0.70710678118654752f;
    float S[25];
#pragma unroll
    for (int i = 0; i < 25; i++) S[i] = base[(64 + i) * SPAD];
    float c[15];
#pragma unroll
    for (int i = 0; i < 15; i++) c[i] = base[(90 + i) * SPAD];

    float A[25];
    A[0] = c[0]; A[6] = c[1]; A[12] = c[2]; A[18] = c[3]; A[24] = c[4];
    A[1] = A[5] = c[5] * is2;   A[2] = A[10] = c[6] * is2;
    A[3] = A[15] = c[7] * is2;  A[4] = A[20] = c[8] * is2;
    A[7] = A[11] = c[9] * is2;  A[8] = A[16] = c[10] * is2;
    A[9] = A[21] = c[11] * is2; A[13] = A[17] = c[12] * is2;
    A[14] = A[22] = c[13] * is2; A[19] = A[23] = c[14] * is2;

    float tr = S[0] + S[6] + S[12] + S[18] + S[24];
    float ia = 1.0f / tr;
    float Y[25], Z[25];
#pragma unroll
    for (int i = 0; i < 25; i++) { Y[i] = S[i] * ia; Z[i] = 0.f; }
    Z[0] = Z[6] = Z[12] = Z[18] = Z[24] = 1.f;
    for (int it = 0; it < 12; it++) {
        float P[25]; mm5(Z, Y, P);
        float Tm[25];
#pragma unroll
        for (int i = 0; i < 25; i++) Tm[i] = -0.5f * P[i];
        Tm[0] += 1.5f; Tm[6] += 1.5f; Tm[12] += 1.5f; Tm[18] += 1.5f; Tm[24] += 1.5f;
        float Yn[25], Zn[25];
        mm5(Y, Tm, Yn); mm5(Tm, Z, Zn);
#pragma unroll
        for (int i = 0; i < 25; i++) { Y[i] = Yn[i]; Z[i] = Zn[i]; }
    }
    float sa = sqrtf(tr);
    float L[25];
#pragma unroll
    for (int i = 0; i < 25; i++) L[i] = Y[i] * sa;

    float E[25];
#pragma unroll
    for (int i = 0; i < 25; i++) E[i] = 0.f;
    E[0] = E[6] = E[12] = E[18] = E[24] = 1.f;
#pragma unroll
    for (int k = 8; k >= 1; k--) {
        float AE[25]; mm5(A, E, AE);
        const float invk = 1.0f / (float)k;
#pragma unroll
        for (int i = 0; i < 25; i++) E[i] = AE[i] * invk;
        E[0] += 1.f; E[6] += 1.f; E[12] += 1.f; E[18] += 1.f; E[24] += 1.f;
    }

    float M1[25], M2[25];
    mm5(L, E, M1); mm5(M1, L, M2);
#pragma unroll
    for (int i = 0; i < 5; i++)
#pragma unroll
        for (int jj = 0; jj < 5; jj++)
            base[(64 + i * 5 + jj) * SPAD] = 0.5f * (M2[i * 5 + jj] + M2[jj * 5 + i]);
}

// ---------------- SDE pair macros: 16 rows (acc[8] ull) --------------------------
#define MP16(WW, IN, KK) do { \
    ull w0 = bplo(WW), w1 = bphi(WW); \
    const ulonglong2* _p0 = (const ulonglong2*)&IN[KK][rbase]; \
    const ulonglong2* _p1 = (const ulonglong2*)&IN[(KK) + 1][rbase]; \
    ulonglong2 _a0 = _p0[0], _a1 = _p0[1], _a2 = _p0[2], _a3 = _p0[3]; \
    ulonglong2 _c0 = _p1[0], _c1 = _p1[1], _c2 = _p1[2], _c3 = _p1[3]; \
    fma2(acc[0], w0, _a0.x); fma2(acc[1], w0, _a0.y); fma2(acc[2], w0, _a1.x); fma2(acc[3], w0, _a1.y); \
    fma2(acc[4], w0, _a2.x); fma2(acc[5], w0, _a2.y); fma2(acc[6], w0, _a3.x); fma2(acc[7], w0, _a3.y); \
    fma2(acc[0], w1, _c0.x); fma2(acc[1], w1, _c0.y); fma2(acc[2], w1, _c1.x); fma2(acc[3], w1, _c1.y); \
    fma2(acc[4], w1, _c2.x); fma2(acc[5], w1, _c2.y); fma2(acc[6], w1, _c3.x); fma2(acc[7], w1, _c3.y); \
} while (0)

#define CTX16(WD, WF, KK) do { \
    ull d0w = bplo(WD), d1w = bphi(WD); \
    ull f0w = bplo(WF), f1w = bphi(WF); \
    const ulonglong2* _p0 = (const ulonglong2*)&inp_s[KK][rbase]; \
    const ulonglong2* _p1 = (const ulonglong2*)&inp_s[(KK) + 1][rbase]; \
    ulonglong2 _a0 = _p0[0], _a1 = _p0[1], _a2 = _p0[2], _a3 = _p0[3]; \
    ulonglong2 _c0 = _p1[0], _c1 = _p1[1], _c2 = _p1[2], _c3 = _p1[3]; \
    fma2(pc_dr[0], d0w, _a0.x); fma2(pc_dr[1], d0w, _a0.y); fma2(pc_dr[2], d0w, _a1.x); fma2(pc_dr[3], d0w, _a1.y); \
    fma2(pc_dr[4], d0w, _a2.x); fma2(pc_dr[5], d0w, _a2.y); fma2(pc_dr[6], d0w, _a3.x); fma2(pc_dr[7], d0w, _a3.y); \
    fma2(pc_dr[0], d1w, _c0.x); fma2(pc_dr[1], d1w, _c0.y); fma2(pc_dr[2], d1w, _c1.x); fma2(pc_dr[3], d1w, _c1.y); \
    fma2(pc_dr[4], d1w, _c2.x); fma2(pc_dr[5], d1w, _c2.y); fma2(pc_dr[6], d1w, _c3.x); fma2(pc_dr[7], d1w, _c3.y); \
    fma2(pc_df[0], f0w, _a0.x); fma2(pc_df[1], f0w, _a0.y); fma2(pc_df[2], f0w, _a1.x); fma2(pc_df[3], f0w, _a1.y); \
    fma2(pc_df[4], f0w, _a2.x); fma2(pc_df[5], f0w, _a2.y); fma2(pc_df[6], f0w, _a3.x); fma2(pc_df[7], f0w, _a3.y); \
    fma2(pc_df[0], f1w, _c0.x); fma2(pc_df[1], f1w, _c0.y); fma2(pc_df[2], f1w, _c1.x); fma2(pc_df[3], f1w, _c1.y); \
    fma2(pc_df[4], f1w, _c2.x); fma2(pc_df[5], f1w, _c2.y); fma2(pc_df[6], f1w, _c3.x); fma2(pc_df[7], f1w, _c3.y); \
} while (0)

__device__ __forceinline__ void mlp64_16(const u32* __restrict__ Wp,
                                         const float (*in_s)[SPAD], float (*out_s)[SPAD],
                                         float bias, int j, int rbase) {
    ull acc[8];
    ull b2 = pack2f(bias);
#pragma unroll
    for (int p = 0; p < 8; p++) acc[p] = b2;
#pragma unroll 2
    for (int kb = 0; kb < 16; kb++) {
        uint4 w4 = ((const uint4*)Wp)[kb * 128 + j];
        int k = kb * 8;
        MP16(w4.x, in_s, k);
        MP16(w4.y, in_s, k + 2);
        MP16(w4.z, in_s, k + 4);
        MP16(w4.w, in_s, k + 6);
    }
#pragma unroll
    for (int p = 0; p < 8; p++) {
        float2 f = unpack2(acc[p]);
        out_s[j][rbase + 2 * p] = f.x * fsig(f.x);
        out_s[j][rbase + 2 * p + 1] = f.y * fsig(f.y);
    }
}

__device__ __forceinline__ void mlp0_16(const u32* __restrict__ Wp,
                                        const float (*in_s)[SPAD], float (*out_s)[SPAD],
                                        const ull* pc, int j, int rbase) {
    ull acc[8];
#pragma unroll
    for (int p = 0; p < 8; p++) acc[p] = pc[p];
#pragma unroll
    for (int kb = 0; kb < 4; kb++) {
        uint4 w4 = ((const uint4*)Wp)[kb * 128 + j];
        int k = 64 + kb * 8;
        MP16(w4.x, in_s, k);
        MP16(w4.y, in_s, k + 2);
        MP16(w4.z, in_s, k + 4);
        MP16(w4.w, in_s, k + 6);
    }
#pragma unroll
    for (int p = 0; p < 8; p++) {
        float2 f = unpack2(acc[p]);
        out_s[j][rbase + 2 * p] = f.x * fsig(f.x);
        out_s[j][rbase + 2 * p + 1] = f.y * fsig(f.y);
    }
}

// ---------------- fused GRU-mma + SDE-scalar kernel: 128 CTAs --------------------
__global__ void __launch_bounds__(256, 1)
fused_kernel(const float* __restrict__ C, const float* __restrict__ dW,
             const float* __restrict__ gbias, const float* __restrict__ gbias_n,
             const float* __restrict__ proj_b,
             const float* __restrict__ db0, const float* __restrict__ db1,
             const float* __restrict__ db2, const float* __restrict__ db3,
             const float* __restrict__ fb0, const float* __restrict__ fb1,
             const float* __restrict__ fb2, float* __restrict__ out) {
    extern __shared__ __align__(16) char sm[];
    const u32 smb = smem_u32(sm);

    const int tid = threadIdx.x;
    const int b0 = blockIdx.x * GRU_RPB;
    const int wid = tid >> 5, lane = tid & 31;
    const int w16 = wid * 16;

    // ================= GRU phase (R14, verified) =================
    {
        const uint4* src = (const uint4*)g_wmma;
        uint4* dst = (uint4*)(sm + WOFF);
        for (int i = tid; i < 10752; i += 256) dst[i] = src[i];
    }
    {
        uint4 z = make_uint4(0, 0, 0, 0);
        uint4* dst = (uint4*)sm;
        for (int i = tid; i < 672; i += 256) dst[i] = z;
    }
    __syncthreads();

    const int rowA = (lane & 7) + ((lane >> 3) & 1) * 8;
    const u32 aB0 = smb + rowA * KSB + (((lane >> 4) & 1) * 8) * 2;
    const u32 aB1 = aB0 + 16 * KSB;
    const int rowB = (lane & 7) + ((lane >> 4) & 1) * 8;
    const u32 bB = smb + WOFF + (wid * 64 + rowB) * KSB + (((lane >> 3) & 1) * 8) * 2;

    float bR[2][2], bZ[2][2], bG[2][2], bN[2][2];
#pragma unroll
    for (int q = 0; q < 2; q++) {
        int j = w16 + q * 8 + (lane & 3) * 2;
        bR[q][0] = gbias[j];        bR[q][1] = gbias[j + 1];
        bZ[q][0] = gbias[128 + j];  bZ[q][1] = gbias[129 + j];
        bG[q][0] = gbias[256 + j];  bG[q][1] = gbias[257 + j];
        bN[q][0] = gbias_n[j];      bN[q][1] = gbias_n[j + 1];
    }

    for (int t = 0; t < T_LEN; t++) {
        for (int i = tid; i < GRU_RPB * 25; i += 256) {
            int r = i / 25, k = i - r * 25;
            int ii = k / 5, jj = k - ii * 5;
            const float* p = C + ((size_t)(b0 + r) * T_LEN + t) * 25;
            float v = 0.5f * (p[ii * 5 + jj] + p[jj * 5 + ii]);
            *(u16*)(sm + r * KSB + k * 2) = bf16u16(v);
        }
        __syncthreads();

        float acc[2][4][2][4];
#pragma unroll
        for (int mi = 0; mi < 2; mi++)
#pragma unroll
            for (int g = 0; g < 4; g++)
#pragma unroll
                for (int q = 0; q < 2; q++) {
                    acc[mi][g][q][0] = 0.f; acc[mi][g][q][1] = 0.f;
                    acc[mi][g][q][2] = 0.f; acc[mi][g][q][3] = 0.f;
                }

#pragma unroll
        for (int kt = 0; kt < 10; kt++) {
            u32 fa0[4], fa1[4];
            LDSM4(fa0[0], fa0[1], fa0[2], fa0[3], aB0 + kt * 32);
            LDSM4(fa1[0], fa1[1], fa1[2], fa1[3], aB1 + kt * 32);
            {
                u32 q0, q1, q2, q3;
                LDSM4(q0, q1, q2, q3, bB + kt * 32);
                MMAF(acc[0][0][0], fa0[0], fa0[1], fa0[2], fa0[3], q0, q1);
                MMAF(acc[0][0][1], fa0[0], fa0[1], fa0[2], fa0[3], q2, q3);
                MMAF(acc[1][0][0], fa1[0], fa1[1], fa1[2], fa1[3], q0, q1);
                MMAF(acc[1][0][1], fa1[0], fa1[1], fa1[2], fa1[3], q2, q3);
            }
            {
                u32 q0, q1, q2, q3;
                LDSM4(q0, q1, q2, q3, bB + 16 * KSB + kt * 32);
                MMAF(acc[0][1][0], fa0[0], fa0[1], fa0[2], fa0[3], q0, q1);
                MMAF(acc[0][1][1], fa0[0], fa0[1], fa0[2], fa0[3], q2, q3);
                MMAF(acc[1][1][0], fa1[0], fa1[1], fa1[2], fa1[3], q0, q1);
                MMAF(acc[1][1][1], fa1[0], fa1[1], fa1[2], fa1[3], q2, q3);
            }
            {
                int g = (kt < 2) ? 2 : 3;
                u32 q0, q1, q2, q3;
                LDSM4(q0, q1, q2, q3, bB + g * 16 * KSB + kt * 32);
                MMAF(acc[0][g][0], fa0[0], fa0[1], fa0[2], fa0[3], q0, q1);
                MMAF(acc[0][g][1], fa0[0], fa0[1], fa0[2], fa0[3], q2, q3);
                MMAF(acc[1][g][0], fa1[0], fa1[1], fa1[2], fa1[3], q0, q1);
                MMAF(acc[1][g][1], fa1[0], fa1[1], fa1[2], fa1[3], q2, q3);
            }
        }

#pragma unroll
        for (int mi = 0; mi < 2; mi++) {
#pragma unroll
            for (int q = 0; q < 2; q++) {
                int jc = w16 + q * 8 + (lane & 3) * 2;
                const float* aR = acc[mi][0][q];
                const float* aZ = acc[mi][1][q];
                const float* aGI = acc[mi][2][q];
                const float* aGH = acc[mi][3][q];
#pragma unroll
                for (int half = 0; half < 2; half++) {
                    int row = mi * 16 + (lane >> 2) + half * 8;
                    u32* hptr = (u32*)(sm + row * KSB + (32 + jc) * 2);
                    u32 hold = *hptr;
                    float ho0 = bf2f((u16)(hold & 0xFFFFu));
                    float ho1 = __uint_as_float(hold & 0xFFFF0000u);
                    int cc = half * 2;
                    float r0 = fsig(aR[cc] + bR[q][0]);
                    float r1 = fsig(aR[cc + 1] + bR[q][1]);
                    float z0 = fsig(aZ[cc] + bZ[q][0]);
                    float z1 = fsig(aZ[cc + 1] + bZ[q][1]);
                    float g0 = ftanh(aGI[cc] + bG[q][0] + r0 * (aGH[cc] + bN[q][0]));
                    float g1 = ftanh(aGI[cc + 1] + bG[q][1] + r1 * (aGH[cc + 1] + bN[q][1]));
                    float h0 = (1.f - z0) * g0 + z0 * ho0;
                    float h1 = (1.f - z1) * g1 + z1 * ho1;
                    *hptr = (u32)bf16u16(h0) | ((u32)bf16u16(h1) << 16);
                }
            }
        }
        __syncthreads();
    }

    // ================= transition: ctx + sigma into SDE smem =================
    // (GRU weights dead from here; SDE arrays overlay them)
    float (*inp_s)[SPAD] = (float (*)[SPAD])(sm + SOFF_INP);
    float (*b1_s)[SPAD]  = (float (*)[SPAD])(sm + SOFF_B1);
    float (*b2_s)[SPAD]  = (float (*)[SPAD])(sm + SOFF_B2);

    // projection: ctx = h @ proj^T + proj_b -> inp_s rows 0..63
    // (reads h from A-tile bytes [0,10752); writes inp_s at bytes >= 10752)
    {
        const int jc = tid & 63, rq = tid >> 6;
        for (int m = 0; m < 8; m++) {
            int r = rq * 8 + m;
            const u16* hrow = (const u16*)(sm + r * KSB + 64);
            float acc = proj_b[jc];
#pragma unroll 4
            for (int k = 0; k < 128; k++) {
                acc += bf2f(hrow[k]) * g_projT[k * 64 + jc];
            }
            inp_s[jc][r] = acc;
        }
    }
    // zero rows 89..95 (read with zero weights by padded L0-dyn kp)
    for (int i = tid; i < 7 * SPAD; i += 256) (&inp_s[89][0])[i] = 0.f;
    // sigma_0 rows 64..88
    for (int i = tid; i < GRU_RPB * 25; i += 256) {
        int r = i / 25, k = i - r * 25;
        int ii = k / 5, jj = k - ii * 5;
        const float* p = C + ((size_t)(b0 + r) * T_LEN + (T_LEN - 1)) * 25;
        inp_s[64 + k][r] = 0.5f * (p[ii * 5 + jj] + p[jj * 5 + ii]);
    }
    __syncthreads();

    // ================= SDE phase (scalar, 32 rows, 16-row groups) ============
    const int j = tid & 127, rg = tid >> 7, rbase = rg * 16;

    ull pc_dr[8], pc_df[8];
    {
        ull bd = pack2f(db0[j]), bf = pack2f(fb0[j]);
#pragma unroll
        for (int p = 0; p < 8; p++) { pc_dr[p] = bd; pc_df[p] = bf; }
#pragma unroll 2
        for (int kb = 0; kb < 8; kb++) {
            uint4 wd4 = ((const uint4*)g_dr0C)[kb * 128 + j];
            uint4 wf4 = ((const uint4*)g_df0C)[kb * 128 + j];
            int k = kb * 8;
            CTX16(wd4.x, wf4.x, k);
            CTX16(wd4.y, wf4.y, k + 2);
            CTX16(wd4.z, wf4.z, k + 4);
            CTX16(wd4.w, wf4.w, k + 6);
        }
    }

    const float v_db1 = db1[j], v_db2 = db2[j];
    const float v_fb1 = fb1[j];

    for (int step = 0; step < NSTEPS; step++) {
        mlp0_16(g_dr0D, inp_s, b1_s, pc_dr, j, rbase);
        __syncthreads();
        mlp64_16(g_dr1P, b1_s, b2_s, v_db1, j, rbase);
        __syncthreads();
        mlp64_16(g_dr2P, b2_s, b1_s, v_db2, j, rbase);
        __syncthreads();
        // drift L3 (480 items, strided) + diff L0 (all threads); disjoint smem
        {
            for (int i = tid; i < GRU_RPB * 15; i += 256) {
                int r = i / 15, k = i - r * 15;
                float acc = db3[k];
#pragma unroll 4
                for (int cc = 0; cc < 128; cc++) acc += b1_s[cc][r] * g_dr3T[cc * 15 + k];
                inp_s[90 + k][r] = acc;
            }
            mlp0_16(g_df0D, inp_s, b2_s, pc_df, j, rbase);
        }
        __syncthreads();
        mlp64_16(g_df1P, b2_s, b1_s, v_fb1, j, rbase);
        __syncthreads();
        // diff L2 + combine
        for (int i = tid; i < GRU_RPB * 15; i += 256) {
            int r = i / 15, k = i - r * 15;
            float acc = fb2[k];
#pragma unroll 4
            for (int cc = 0; cc < 128; cc++) acc += b1_s[cc][r] * g_df2T[cc * 15 + k];
            float sp = (acc > 20.f) ? acc : log1pf(__expf(acc));
            float dwv = dW[((size_t)(b0 + r) * NSTEPS + step) * DDIM + k];
            inp_s[90 + k][r] = inp_s[90 + k][r] * DT_C + sp * dwv;
        }
        __syncthreads();
        // geometric update: 32 samples on full warp 0
        if (tid < GRU_RPB) geo_update(&inp_s[0][tid]);
        __syncthreads();
    }

    for (int i = tid; i < GRU_RPB * 25; i += 256) {
        int r = i / 25, k = i - r * 25;
        out[(size_t)(b0 + r) * 25 + k] = inp_s[64 + k][r];
    }
}

// ---------------- launch ---------------------------------------------------------
extern "C" void kernel_launch(void* const* d_in, const int* in_sizes, int n_in,
                              void* d_out, int out_size) {
    const float* ctx_spd = (const float*)d_in[0];
    const float* dWp     = (const float*)d_in[1];
    const float* wih     = (const float*)d_in[2];
    const float* whh     = (const float*)d_in[3];
    const float* gbias   = (const float*)d_in[4];
    const float* gbias_n = (const float*)d_in[5];
    const float* projw   = (const float*)d_in[6];
    const float* projb   = (const float*)d_in[7];
    const float* dw0 = (const float*)d_in[8];  const float* db0 = (const float*)d_in[9];
    const float* dw1 = (const float*)d_in[10]; const float* db1 = (const float*)d_in[11];
    const float* dw2 = (const float*)d_in[12]; const float* db2 = (const float*)d_in[13];
    const float* dw3 = (const float*)d_in[14]; const float* db3 = (const float*)d_in[15];
    const float* fw0 = (const float*)d_in[16]; const float* fb0 = (const float*)d_in[17];
    const float* fw1 = (const float*)d_in[18]; const float* fb1 = (const float*)d_in[19];
    const float* fw2 = (const float*)d_in[20]; const float* fb2 = (const float*)d_in[21];
    float* out = (float*)d_out;

    static int smem_set = 0;
    if (!smem_set) {
        cudaFuncSetAttribute(fused_kernel, cudaFuncAttributeMaxDynamicSharedMemorySize, GRU_SMEM);
        smem_set = 1;
    }

    prep_kernel<<<64, 256>>>(wih, whh, projw, dw0, dw1, dw2, dw3, fw0, fw1, fw2);
    fused_kernel<<<GRU_NBLK, 256, GRU_SMEM>>>(ctx_spd, dWp, gbias, gbias_n, projb,
                                              db0, db1, db2, db3, fb0, fb1, fb2, out);
}

// round 17
// speedup vs baseline: 1.1844x; 1.1844x over previous
#include <cuda_runtime.h>
#include <cuda_bf16.h>
#include <math.h>

#define B_TOT 4096
#define T_LEN 32
#define DDIM 15
#define NSTEPS 5
#define DT_C 0.2f
#define RPB 16
#define NBLK (B_TOT / RPB)
#define PAD 20

// GRU mma kernel config (R14, verified)
#define GRU_RPB 32
#define GRU_NBLK (B_TOT / GRU_RPB)
#define KS 168
#define KSB 336
#define WOFF 10752
#define GRU_SMEM (10752 + 512 * KSB)

// SDE dynamic smem layout (float offsets)
#define FO_INP  0          // [106][20]
#define FO_DR1  2120       // [128][20]
#define FO_DR2  4680
#define FO_DF1  7240
#define FO_DF2  9800
#define FO_SCR  12360      // [15][20]  diff softplus out
#define FO_SC2  12660      // [15][20]  drift_c
#define SDE_SMEM (12960 * 4)

typedef unsigned long long ull;
typedef unsigned int u32;
typedef unsigned short u16;

__device__ __forceinline__ float tanhapx(float x) {
    float y; asm("tanh.approx.f32 %0, %1;" : "=f"(y) : "f"(x)); return y;
}
__device__ __forceinline__ float fsig(float x) { return fmaf(0.5f, tanhapx(0.5f * x), 0.5f); }
__device__ __forceinline__ float ftanh(float x) { return tanhapx(x); }
__device__ __forceinline__ float bf2f(u16 b) { return __uint_as_float(((u32)b) << 16); }

// ---------------- packed f32x2 helpers -------------------------------------------
__device__ __forceinline__ void fma2(ull& acc, ull a, ull b) {
    asm("fma.rn.f32x2 %0, %1, %2, %0;" : "+l"(acc) : "l"(a), "l"(b));
}
__device__ __forceinline__ ull pack2f(float w) {
    ull r; asm("mov.b64 %0, {%1, %1};" : "=l"(r) : "r"(__float_as_uint(w))); return r;
}
__device__ __forceinline__ ull bplo(u32 u) {
    u32 f = u << 16; ull r; asm("mov.b64 %0, {%1, %1};" : "=l"(r) : "r"(f)); return r;
}
__device__ __forceinline__ ull bphi(u32 u) {
    u32 f = u & 0xFFFF0000u; ull r; asm("mov.b64 %0, {%1, %1};" : "=l"(r) : "r"(f)); return r;
}
__device__ __forceinline__ float2 unpack2(ull v) {
    float2 f; asm("mov.b64 {%0, %1}, %2;" : "=f"(f.x), "=f"(f.y) : "l"(v)); return f;
}

// ---------------- weight scratch ------------------------------------------------
__device__ __align__(16) u32 g_dr0C[4096];
__device__ __align__(16) u32 g_df0C[4096];
__device__ __align__(16) u32 g_dr0D[2048];
__device__ __align__(16) u32 g_df0D[2048];
__device__ __align__(16) u32 g_dr1P[8192];
__device__ __align__(16) u32 g_dr2P[8192];
__device__ __align__(16) u32 g_df1P[8192];
__device__ float g_dr3T[128 * 15];
__device__ float g_df2T[128 * 15];
__device__ float g_projT[128 * 64];
__device__ float g_ctx[B_TOT * 64];
__device__ __align__(16) u16 g_wmma[512 * KS];

__device__ __forceinline__ u32 bfbits(float w) {
    __nv_bfloat16 h = __float2bfloat16(w);
    return (u32)__bfloat16_as_ushort(h);
}
__device__ __forceinline__ u16 bf16u16(float w) {
    __nv_bfloat16 h = __float2bfloat16(w);
    return __bfloat16_as_ushort(h);
}

// ---------------- prep (R14, verified) -------------------------------------------
__global__ void prep_kernel(const float* __restrict__ wih, const float* __restrict__ whh,
                            const float* __restrict__ proj,
                            const float* __restrict__ d0, const float* __restrict__ d1,
                            const float* __restrict__ d2, const float* __restrict__ d3,
                            const float* __restrict__ f0, const float* __restrict__ f1,
                            const float* __restrict__ f2) {
    int tid = blockIdx.x * blockDim.x + threadIdx.x;
    int nt = gridDim.x * blockDim.x;

    for (int i = tid; i < 512 * KS; i += nt) {
        int n = i / KS, k = i - n * KS;
        int chunk = n >> 6, rem = n & 63, gate = rem >> 4, jr = rem & 15;
        int j = chunk * 16 + jr;
        float v = 0.f;
        if (gate == 0) {
            if (k < 25) v = wih[j * 25 + k];
            else if (k >= 32 && k < 160) v = whh[j * 128 + (k - 32)];
        } else if (gate == 1) {
            if (k < 25) v = wih[(128 + j) * 25 + k];
            else if (k >= 32 && k < 160) v = whh[(128 + j) * 128 + (k - 32)];
        } else if (gate == 2) {
            if (k < 25) v = wih[(256 + j) * 25 + k];
        } else {
            if (k >= 32 && k < 160) v = whh[(256 + j) * 128 + (k - 32)];
        }
        g_wmma[i] = bf16u16(v);
    }

    for (int i = tid; i < 4096; i += nt) {
        int t = i & 3, j = (i >> 2) & 127, kb = i >> 9;
        int kp = kb * 4 + t;
        g_dr0C[i] = bfbits(d0[j * 89 + 25 + 2 * kp]) | (bfbits(d0[j * 89 + 26 + 2 * kp]) << 16);
        g_df0C[i] = bfbits(f0[j * 89 + 25 + 2 * kp]) | (bfbits(f0[j * 89 + 26 + 2 * kp]) << 16);
    }
    for (int i = tid; i < 2048; i += nt) {
        int t = i & 3, j = (i >> 2) & 127, kb = i >> 9;
        int kp = kb * 4 + t, k0 = 2 * kp, k1 = 2 * kp + 1;
        float a0 = (k0 < 25) ? d0[j * 89 + k0] : 0.f;
        float a1 = (k1 < 25) ? d0[j * 89 + k1] : 0.f;
        g_dr0D[i] = bfbits(a0) | (bfbits(a1) << 16);
        float c0 = (k0 < 25) ? f0[j * 89 + k0] : 0.f;
        float c1 = (k1 < 25) ? f0[j * 89 + k1] : 0.f;
        g_df0D[i] = bfbits(c0) | (bfbits(c1) << 16);
    }
    for (int i = tid; i < 8192; i += nt) {
        int t = i & 3, j = (i >> 2) & 127, kb = i >> 9;
        int kp = kb * 4 + t;
        g_dr1P[i] = bfbits(d1[j * 128 + 2 * kp]) | (bfbits(d1[j * 128 + 2 * kp + 1]) << 16);
        g_dr2P[i] = bfbits(d2[j * 128 + 2 * kp]) | (bfbits(d2[j * 128 + 2 * kp + 1]) << 16);
        g_df1P[i] = bfbits(f1[j * 128 + 2 * kp]) | (bfbits(f1[j * 128 + 2 * kp + 1]) << 16);
    }
    for (int i = tid; i < 15 * 128; i += nt) { int o = i >> 7, k = i & 127; g_dr3T[k * 15 + o] = d3[i]; }
    for (int i = tid; i < 15 * 128; i += nt) { int o = i >> 7, k = i & 127; g_df2T[k * 15 + o] = f2[i]; }
    for (int i = tid; i < 64 * 128; i += nt) { int o = i >> 7, k = i & 127; g_projT[k * 64 + o] = proj[i]; }
}

// ---------------- mma helpers ----------------------------------------------------
__device__ __forceinline__ u32 smem_u32(const void* p) {
    u32 a;
    asm("{ .reg .u64 t; cvta.to.shared.u64 t, %1; cvt.u32.u64 %0, t; }" : "=r"(a) : "l"(p));
    return a;
}

#define LDSM4(R0, R1, R2, R3, ADDR) \
    asm volatile("ldmatrix.sync.aligned.m8n8.x4.shared.b16 {%0,%1,%2,%3}, [%4];" \
        : "=r"(R0), "=r"(R1), "=r"(R2), "=r"(R3) : "r"(ADDR))

#define MMAF(CACC, A0, A1, A2, A3, B0, B1) \
    asm volatile("mma.sync.aligned.m16n8k16.row.col.f32.bf16.bf16.f32 " \
        "{%0,%1,%2,%3}, {%4,%5,%6,%7}, {%8,%9}, {%0,%1,%2,%3};" \
        : "+f"((CACC)[0]), "+f"((CACC)[1]), "+f"((CACC)[2]), "+f"((CACC)[3]) \
        : "r"(A0), "r"(A1), "r"(A2), "r"(A3), "r"(B0), "r"(B1))

// ---------------- GRU mma.sync kernel (R14, verified) ----------------------------
__global__ void __launch_bounds__(256, 1)
gru_mma_kernel(const float* __restrict__ C,
               const float* __restrict__ gbias, const float* __restrict__ gbias_n,
               const float* __restrict__ proj_b) {
    extern __shared__ __align__(16) char sm[];
    const u32 smb = smem_u32(sm);

    const int tid = threadIdx.x;
    const int b0 = blockIdx.x * GRU_RPB;
    const int wid = tid >> 5, lane = tid & 31;
    const int w16 = wid * 16;

    {
        const uint4* src = (const uint4*)g_wmma;
        uint4* dst = (uint4*)(sm + WOFF);
        for (int i = tid; i < 10752; i += 256) dst[i] = src[i];
    }
    {
        uint4 z = make_uint4(0, 0, 0, 0);
        uint4* dst = (uint4*)sm;
        for (int i = tid; i < 672; i += 256) dst[i] = z;
    }
    __syncthreads();

    const int rowA = (lane & 7) + ((lane >> 3) & 1) * 8;
    const u32 aB0 = smb + rowA * KSB + (((lane >> 4) & 1) * 8) * 2;
    const u32 aB1 = aB0 + 16 * KSB;
    const int rowB = (lane & 7) + ((lane >> 4) & 1) * 8;
    const u32 bB = smb + WOFF + (wid * 64 + rowB) * KSB + (((lane >> 3) & 1) * 8) * 2;

    float bR[2][2], bZ[2][2], bG[2][2], bN[2][2];
#pragma unroll
    for (int q = 0; q < 2; q++) {
        int j = w16 + q * 8 + (lane & 3) * 2;
        bR[q][0] = gbias[j];        bR[q][1] = gbias[j + 1];
        bZ[q][0] = gbias[128 + j];  bZ[q][1] = gbias[129 + j];
        bG[q][0] = gbias[256 + j];  bG[q][1] = gbias[257 + j];
        bN[q][0] = gbias_n[j];      bN[q][1] = gbias_n[j + 1];
    }

    for (int t = 0; t < T_LEN; t++) {
        for (int i = tid; i < GRU_RPB * 25; i += 256) {
            int r = i / 25, k = i - r * 25;
            int ii = k / 5, jj = k - ii * 5;
            const float* p = C + ((size_t)(b0 + r) * T_LEN + t) * 25;
            float v = 0.5f * (p[ii * 5 + jj] + p[jj * 5 + ii]);
            *(u16*)(sm + r * KSB + k * 2) = bf16u16(v);
        }
        __syncthreads();

        float acc[2][4][2][4];
#pragma unroll
        for (int mi = 0; mi < 2; mi++)
#pragma unroll
            for (int g = 0; g < 4; g++)
#pragma unroll
                for (int q = 0; q < 2; q++) {
                    acc[mi][g][q][0] = 0.f; acc[mi][g][q][1] = 0.f;
                    acc[mi][g][q][2] = 0.f; acc[mi][g][q][3] = 0.f;
                }

#pragma unroll
        for (int kt = 0; kt < 10; kt++) {
            u32 fa0[4], fa1[4];
            LDSM4(fa0[0], fa0[1], fa0[2], fa0[3], aB0 + kt * 32);
            LDSM4(fa1[0], fa1[1], fa1[2], fa1[3], aB1 + kt * 32);
            {
                u32 q0, q1, q2, q3;
                LDSM4(q0, q1, q2, q3, bB + kt * 32);
                MMAF(acc[0][0][0], fa0[0], fa0[1], fa0[2], fa0[3], q0, q1);
                MMAF(acc[0][0][1], fa0[0], fa0[1], fa0[2], fa0[3], q2, q3);
                MMAF(acc[1][0][0], fa1[0], fa1[1], fa1[2], fa1[3], q0, q1);
                MMAF(acc[1][0][1], fa1[0], fa1[1], fa1[2], fa1[3], q2, q3);
            }
            {
                u32 q0, q1, q2, q3;
                LDSM4(q0, q1, q2, q3, bB + 16 * KSB + kt * 32);
                MMAF(acc[0][1][0], fa0[0], fa0[1], fa0[2], fa0[3], q0, q1);
                MMAF(acc[0][1][1], fa0[0], fa0[1], fa0[2], fa0[3], q2, q3);
                MMAF(acc[1][1][0], fa1[0], fa1[1], fa1[2], fa1[3], q0, q1);
                MMAF(acc[1][1][1], fa1[0], fa1[1], fa1[2], fa1[3], q2, q3);
            }
            {
                int g = (kt < 2) ? 2 : 3;
                u32 q0, q1, q2, q3;
                LDSM4(q0, q1, q2, q3, bB + g * 16 * KSB + kt * 32);
                MMAF(acc[0][g][0], fa0[0], fa0[1], fa0[2], fa0[3], q0, q1);
                MMAF(acc[0][g][1], fa0[0], fa0[1], fa0[2], fa0[3], q2, q3);
                MMAF(acc[1][g][0], fa1[0], fa1[1], fa1[2], fa1[3], q0, q1);
                MMAF(acc[1][g][1], fa1[0], fa1[1], fa1[2], fa1[3], q2, q3);
            }
        }

#pragma unroll
        for (int mi = 0; mi < 2; mi++) {
#pragma unroll
            for (int q = 0; q < 2; q++) {
                int jc = w16 + q * 8 + (lane & 3) * 2;
                const float* aR = acc[mi][0][q];
                const float* aZ = acc[mi][1][q];
                const float* aGI = acc[mi][2][q];
                const float* aGH = acc[mi][3][q];
#pragma unroll
                for (int half = 0; half < 2; half++) {
                    int row = mi * 16 + (lane >> 2) + half * 8;
                    u32* hptr = (u32*)(sm + row * KSB + (32 + jc) * 2);
                    u32 hold = *hptr;
                    float ho0 = bf2f((u16)(hold & 0xFFFFu));
                    float ho1 = __uint_as_float(hold & 0xFFFF0000u);
                    int cc = half * 2;
                    float r0 = fsig(aR[cc] + bR[q][0]);
                    float r1 = fsig(aR[cc + 1] + bR[q][1]);
                    float z0 = fsig(aZ[cc] + bZ[q][0]);
                    float z1 = fsig(aZ[cc + 1] + bZ[q][1]);
                    float g0 = ftanh(aGI[cc] + bG[q][0] + r0 * (aGH[cc] + bN[q][0]));
                    float g1 = ftanh(aGI[cc + 1] + bG[q][1] + r1 * (aGH[cc + 1] + bN[q][1]));
                    float h0 = (1.f - z0) * g0 + z0 * ho0;
                    float h1 = (1.f - z1) * g1 + z1 * ho1;
                    *hptr = (u32)bf16u16(h0) | ((u32)bf16u16(h1) << 16);
                }
            }
        }
        __syncthreads();
    }

    {
        const int jc = tid & 63, rq = tid >> 6;
        for (int m = 0; m < 8; m++) {
            int r = rq * 8 + m;
            const u16* hrow = (const u16*)(sm + r * KSB + 64);
            float acc = proj_b[jc];
#pragma unroll 4
            for (int k = 0; k < 128; k++) {
                acc += bf2f(hrow[k]) * g_projT[k * 64 + jc];
            }
            g_ctx[(size_t)(b0 + r) * 64 + jc] = acc;
        }
    }
}

// ---------------- 5x5 helpers / geo ----------------------------------------------
__device__ __forceinline__ void mm5(const float* A, const float* Bm, float* Cm) {
#pragma unroll
    for (int i = 0; i < 5; i++) {
#pragma unroll
        for (int jj = 0; jj < 5; jj++) {
            float s = A[i * 5] * Bm[jj];
#pragma unroll
            for (int k = 1; k < 5; k++) s += A[i * 5 + k] * Bm[k * 5 + jj];
            Cm[i * 5 + jj] = s;
        }
    }
}

// base = &inp[0*PAD + lane]; sigma rows 64..88, coeff rows 90..104, stride PAD
__device__ void geo_update(float* base) {
    const float is2 = 0.70710678118654752f;
    float S[25];
#pragma unroll
    for (int i = 0; i < 25; i++) S[i] = base[(64 + i) * PAD];
    float c[15];
#pragma unroll
    for (int i = 0; i < 15; i++) c[i] = base[(90 + i) * PAD];

    float A[25];
    A[0] = c[0]; A[6] = c[1]; A[12] = c[2]; A[18] = c[3]; A[24] = c[4];
    A[1] = A[5] = c[5] * is2;   A[2] = A[10] = c[6] * is2;
    A[3] = A[15] = c[7] * is2;  A[4] = A[20] = c[8] * is2;
    A[7] = A[11] = c[9] * is2;  A[8] = A[16] = c[10] * is2;
    A[9] = A[21] = c[11] * is2; A[13] = A[17] = c[12] * is2;
    A[14] = A[22] = c[13] * is2; A[19] = A[23] = c[14] * is2;

    float tr = S[0] + S[6] + S[12] + S[18] + S[24];
    float ia = 1.0f / tr;
    float Y[25], Z[25];
#pragma unroll
    for (int i = 0; i < 25; i++) { Y[i] = S[i] * ia; Z[i] = 0.f; }
    Z[0] = Z[6] = Z[12] = Z[18] = Z[24] = 1.f;
    for (int it = 0; it < 12; it++) {
        float P[25]; mm5(Z, Y, P);
        float Tm[25];
#pragma unroll
        for (int i = 0; i < 25; i++) Tm[i] = -0.5f * P[i];
        Tm[0] += 1.5f; Tm[6] += 1.5f; Tm[12] += 1.5f; Tm[18] += 1.5f; Tm[24] += 1.5f;
        float Yn[25], Zn[25];
        mm5(Y, Tm, Yn); mm5(Tm, Z, Zn);
#pragma unroll
        for (int i = 0; i < 25; i++) { Y[i] = Yn[i]; Z[i] = Zn[i]; }
    }
    float sa = sqrtf(tr);
    float L[25];
#pragma unroll
    for (int i = 0; i < 25; i++) L[i] = Y[i] * sa;

    float E[25];
#pragma unroll
    for (int i = 0; i < 25; i++) E[i] = 0.f;
    E[0] = E[6] = E[12] = E[18] = E[24] = 1.f;
#pragma unroll
    for (int k = 8; k >= 1; k--) {
        float AE[25]; mm5(A, E, AE);
        const float invk = 1.0f / (float)k;
#pragma unroll
        for (int i = 0; i < 25; i++) E[i] = AE[i] * invk;
        E[0] += 1.f; E[6] += 1.f; E[12] += 1.f; E[18] += 1.f; E[24] += 1.f;
    }

    float M1[25], M2[25];
    mm5(L, E, M1); mm5(M1, L, M2);
#pragma unroll
    for (int i = 0; i < 5; i++)
#pragma unroll
        for (int jj = 0; jj < 5; jj++)
            base[(64 + i * 5 + jj) * PAD] = 0.5f * (M2[i * 5 + jj] + M2[jj * 5 + i]);
}

// ---------------- SDE 16-row pair macros (rbase = 0) -----------------------------
#define MP16(WW, IN, KK) do { \
    ull w0 = bplo(WW), w1 = bphi(WW); \
    const ulonglong2* _p0 = (const ulonglong2*)(IN + (KK) * PAD); \
    const ulonglong2* _p1 = (const ulonglong2*)(IN + ((KK) + 1) * PAD); \
    ulonglong2 _a0 = _p0[0], _a1 = _p0[1], _a2 = _p0[2], _a3 = _p0[3]; \
    ulonglong2 _c0 = _p1[0], _c1 = _p1[1], _c2 = _p1[2], _c3 = _p1[3]; \
    fma2(acc[0], w0, _a0.x); fma2(acc[1], w0, _a0.y); fma2(acc[2], w0, _a1.x); fma2(acc[3], w0, _a1.y); \
    fma2(acc[4], w0, _a2.x); fma2(acc[5], w0, _a2.y); fma2(acc[6], w0, _a3.x); fma2(acc[7], w0, _a3.y); \
    fma2(acc[0], w1, _c0.x); fma2(acc[1], w1, _c0.y); fma2(acc[2], w1, _c1.x); fma2(acc[3], w1, _c1.y); \
    fma2(acc[4], w1, _c2.x); fma2(acc[5], w1, _c2.y); fma2(acc[6], w1, _c3.x); fma2(acc[7], w1, _c3.y); \
} while (0)

#define TBAR(ID) asm volatile("bar.sync %0, 128;" :: "r"(ID) : "memory")

__device__ __forceinline__ void mlp64_t(const u32* __restrict__ Wp,
                                        const float* in, float* out,
                                        float bias, int j) {
    ull acc[8];
    ull b2 = pack2f(bias);
#pragma unroll
    for (int p = 0; p < 8; p++) acc[p] = b2;
#pragma unroll 2
    for (int kb = 0; kb < 16; kb++) {
        uint4 w4 = ((const uint4*)Wp)[kb * 128 + j];
        int k = kb * 8;
        MP16(w4.x, in, k);
        MP16(w4.y, in, k + 2);
        MP16(w4.z, in, k + 4);
        MP16(w4.w, in, k + 6);
    }
#pragma unroll
    for (int p = 0; p < 8; p++) {
        float2 f = unpack2(acc[p]);
        out[j * PAD + 2 * p] = f.x * fsig(f.x);
        out[j * PAD + 2 * p + 1] = f.y * fsig(f.y);
    }
}

__device__ __forceinline__ void mlp0_t(const u32* __restrict__ Wp,
                                       const float* inp, float* out,
                                       const ull* pc, int j) {
    ull acc[8];
#pragma unroll
    for (int p = 0; p < 8; p++) acc[p] = pc[p];
#pragma unroll
    for (int kb = 0; kb < 4; kb++) {
        uint4 w4 = ((const uint4*)Wp)[kb * 128 + j];
        int k = 64 + kb * 8;
        MP16(w4.x, inp, k);
        MP16(w4.y, inp, k + 2);
        MP16(w4.z, inp, k + 4);
        MP16(w4.w, inp, k + 6);
    }
#pragma unroll
    for (int p = 0; p < 8; p++) {
        float2 f = unpack2(acc[p]);
        out[j * PAD + 2 * p] = f.x * fsig(f.x);
        out[j * PAD + 2 * p + 1] = f.y * fsig(f.y);
    }
}

// ---------------- SDE kernel: warp-specialized drift/diff teams ------------------
__global__ void __launch_bounds__(256, 2) sde_kernel(
    const float* __restrict__ C, const float* __restrict__ dW,
    const float* __restrict__ db0, const float* __restrict__ db1,
    const float* __restrict__ db2, const float* __restrict__ db3,
    const float* __restrict__ fb0, const float* __restrict__ fb1,
    const float* __restrict__ fb2, float* __restrict__ out) {
    extern __shared__ __align__(16) float dsm[];
    float* inp = dsm + FO_INP;
    float* dr1 = dsm + FO_DR1;
    float* dr2 = dsm + FO_DR2;
    float* df1 = dsm + FO_DF1;
    float* df2 = dsm + FO_DF2;
    float* scr = dsm + FO_SCR;
    float* sc2 = dsm + FO_SC2;

    const int tid = threadIdx.x;
    const int b0 = blockIdx.x * RPB;
    const int team = tid >> 7;         // 0 = drift, 1 = diff
    const int j = tid & 127;

    // init: ctx rows 0..63, zero rows 89..95, sigma rows 64..88
    for (int i = tid; i < RPB * 64; i += 256) {
        int r = i >> 6, k = i & 63;
        inp[k * PAD + r] = g_ctx[(size_t)(b0 + r) * 64 + k];
    }
    for (int i = tid; i < 7 * PAD; i += 256) inp[89 * PAD + i] = 0.f;
    for (int i = tid; i < RPB * 25; i += 256) {
        int r = i / 25, k = i - r * 25;
        int ii = k / 5, jj = k - ii * 5;
        const float* p = C + ((size_t)(b0 + r) * T_LEN + (T_LEN - 1)) * 25;
        inp[(64 + k) * PAD + r] = 0.5f * (p[ii * 5 + jj] + p[jj * 5 + ii]);
    }
    __syncthreads();

    // team-specific ctx partial sums (seed for L0)
    ull pc[8];
    {
        ull b = pack2f(team ? fb0[j] : db0[j]);
#pragma unroll
        for (int p = 0; p < 8; p++) pc[p] = b;
        const u32* WC = team ? g_df0C : g_dr0C;
#pragma unroll 2
        for (int kb = 0; kb < 8; kb++) {
            uint4 w4 = ((const uint4*)WC)[kb * 128 + j];
            int k = kb * 8;
            { ull* acc = pc; MP16(w4.x, inp, k); }
            { ull* acc = pc; MP16(w4.y, inp, k + 2); }
            { ull* acc = pc; MP16(w4.z, inp, k + 4); }
            { ull* acc = pc; MP16(w4.w, inp, k + 6); }
        }
    }

    const float vb1 = team ? fb1[j] : db1[j];
    const float vb2 = team ? 0.f : db2[j];

    for (int step = 0; step < NSTEPS; step++) {
        if (team == 0) {
            // drift chain: L0 -> L1 -> L2 -> L3
            mlp0_t(g_dr0D, inp, dr1, pc, j);
            TBAR(1);
            mlp64_t(g_dr1P, dr1, dr2, vb1, j);
            TBAR(1);
            mlp64_t(g_dr2P, dr2, dr1, vb2, j);
            TBAR(1);
            for (int i = j; i < RPB * 15; i += 128) {
                int r = i / 15, k = i - r * 15;
                float acc = db3[k];
#pragma unroll 4
                for (int cc = 0; cc < 128; cc++) acc += dr1[cc * PAD + r] * g_dr3T[cc * 15 + k];
                sc2[k * PAD + r] = acc;   // raw drift_c
            }
        } else {
            // diff chain: L0 -> L1 -> L2out(softplus)
            mlp0_t(g_df0D, inp, df1, pc, j);
            TBAR(2);
            mlp64_t(g_df1P, df1, df2, vb1, j);
            TBAR(2);
            for (int i = j; i < RPB * 15; i += 128) {
                int r = i / 15, k = i - r * 15;
                float acc = fb2[k];
#pragma unroll 4
                for (int cc = 0; cc < 128; cc++) acc += df2[cc * PAD + r] * g_df2T[cc * 15 + k];
                float sp = (acc > 20.f) ? acc : log1pf(__expf(acc));
                scr[k * PAD + r] = sp;
            }
        }
        __syncthreads();
        // combine: coeff = drift_c*DT + softplus*dW -> inp rows 90..104
        for (int i = tid; i < RPB * 15; i += 256) {
            int r = i / 15, k = i - r * 15;
            float dwv = dW[((size_t)(b0 + r) * NSTEPS + step) * DDIM + k];
            inp[(90 + k) * PAD + r] = sc2[k * PAD + r] * DT_C + scr[k * PAD + r] * dwv;
        }
        __syncthreads();
        if (tid < RPB) geo_update(&inp[tid]);
        __syncthreads();
    }

    for (int i = tid; i < RPB * 25; i += 256) {
        int r = i / 25, k = i - r * 25;
        out[(size_t)(b0 + r) * 25 + k] = inp[(64 + k) * PAD + r];
    }
}

// ---------------- launch ---------------------------------------------------------
extern "C" void kernel_launch(void* const* d_in, const int* in_sizes, int n_in,
                              void* d_out, int out_size) {
    const float* ctx_spd = (const float*)d_in[0];
    const float* dWp     = (const float*)d_in[1];
    const float* wih     = (const float*)d_in[2];
    const float* whh     = (const float*)d_in[3];
    const float* gbias   = (const float*)d_in[4];
    const float* gbias_n = (const float*)d_in[5];
    const float* projw   = (const float*)d_in[6];
    const float* projb   = (const float*)d_in[7];
    const float* dw0 = (const float*)d_in[8];  const float* db0 = (const float*)d_in[9];
    const float* dw1 = (const float*)d_in[10]; const float* db1 = (const float*)d_in[11];
    const float* dw2 = (const float*)d_in[12]; const float* db2 = (const float*)d_in[13];
    const float* dw3 = (const float*)d_in[14]; const float* db3 = (const float*)d_in[15];
    const float* fw0 = (const float*)d_in[16]; const float* fb0 = (const float*)d_in[17];
    const float* fw1 = (const float*)d_in[18]; const float* fb1 = (const float*)d_in[19];
    const float* fw2 = (const float*)d_in[20]; const float* fb2 = (const float*)d_in[21];
    float* out = (float*)d_out;

    static int smem_set = 0;
    if (!smem_set) {
        cudaFuncSetAttribute(gru_mma_kernel, cudaFuncAttributeMaxDynamicSharedMemorySize, GRU_SMEM);
        cudaFuncSetAttribute(sde_kernel, cudaFuncAttributeMaxDynamicSharedMemorySize, SDE_SMEM);
        smem_set = 1;
    }

    prep_kernel<<<64, 256>>>(wih, whh, projw, dw0, dw1, dw2, dw3, fw0, fw1, fw2);
    gru_mma_kernel<<<GRU_NBLK, 256, GRU_SMEM>>>(ctx_spd, gbias, gbias_n, projb);
    sde_kernel<<<NBLK, 256, SDE_SMEM>>>(ctx_spd, dWp, db0, db1, db2, db3,
                                        fb0, fb1, fb2, out);
}